// round 2
// baseline (speedup 1.0000x reference)
#include <cuda_runtime.h>
#include <math.h>

#define F 64
#define N_CAP   50176
#define TOT_CAP 852992   // E + N with margin
#define RS 68            // smem row stride (floats): 272B = 16B-aligned per row

// ---------------- device scratch (static globals; no runtime alloc) ----------------
__device__ float g_asrc[N_CAP * F];
__device__ float g_adst[N_CAP * F];
__device__ float g_v   [N_CAP * F];
__device__ float g_ssum[N_CAP * F];
__device__ float g_oacc[N_CAP * F];
__device__ float g_eexp[TOT_CAP * F];   // exp(alpha) per edge
__device__ float g_tvd [TOT_CAP * F];   // v[src] + delta per edge

// ---------------- 4x4 register-tiled 64x64x64 smem GEMM (accumulating) ----------------
__device__ __forceinline__ void gemm64_acc(const float* __restrict__ As,  // [64][RS]
                                           const float* __restrict__ Bs,  // [64][64]
                                           int r0, int c0, float acc[4][4])
{
#pragma unroll 4
    for (int k = 0; k < 64; k++) {
        float4 b = *(const float4*)(Bs + k * 64 + c0);
        float a0 = As[(r0 + 0) * RS + k];
        float a1 = As[(r0 + 1) * RS + k];
        float a2 = As[(r0 + 2) * RS + k];
        float a3 = As[(r0 + 3) * RS + k];
        acc[0][0] += a0 * b.x; acc[0][1] += a0 * b.y; acc[0][2] += a0 * b.z; acc[0][3] += a0 * b.w;
        acc[1][0] += a1 * b.x; acc[1][1] += a1 * b.y; acc[1][2] += a1 * b.z; acc[1][3] += a1 * b.w;
        acc[2][0] += a2 * b.x; acc[2][1] += a2 * b.y; acc[2][2] += a2 * b.z; acc[2][3] += a2 * b.w;
        acc[3][0] += a3 * b.x; acc[3][1] += a3 * b.y; acc[3][2] += a3 * b.z; acc[3][3] += a3 * b.w;
    }
}

// ---------------- K1: h = relu(x@Win+b); a_src=h@Wsrc; a_dst=h@Wdst; v=h@Wlin ----------------
__global__ void __launch_bounds__(256) k_proj(
    const float* __restrict__ x,
    const float* __restrict__ Win, const float* __restrict__ bin,
    const float* __restrict__ Wsrc, const float* __restrict__ Wdst,
    const float* __restrict__ Wlin, int N)
{
    extern __shared__ float sm[];
    float* sWin = sm;
    float* sWs  = sWin + 4096;
    float* sWd  = sWs  + 4096;
    float* sWl  = sWd  + 4096;
    float* sb   = sWl  + 4096;
    float* xs   = sb + 64;          // [64][RS]
    float* hs   = xs + 64 * RS;     // [64][RS]
    const int tid = threadIdx.x;

    for (int i = tid; i < 4096; i += 256) {
        sWin[i] = Win[i]; sWs[i] = Wsrc[i]; sWd[i] = Wdst[i]; sWl[i] = Wlin[i];
    }
    if (tid < 64) sb[tid] = bin[tid];

    const int base = blockIdx.x * 64;
    for (int i = tid; i < 1024; i += 256) {
        int r = i >> 4, c4 = (i & 15) << 2;
        int row = base + r;
        float4 v = (row < N) ? *(const float4*)(x + (size_t)row * 64 + c4)
                             : make_float4(0.f, 0.f, 0.f, 0.f);
        *(float4*)(xs + r * RS + c4) = v;
    }
    __syncthreads();

    const int tr = tid >> 4, tc = tid & 15, r0 = tr * 4, c0 = tc * 4;
    float acc[4][4];

    // h
#pragma unroll
    for (int i = 0; i < 4; i++)
#pragma unroll
        for (int j = 0; j < 4; j++) acc[i][j] = sb[c0 + j];
    gemm64_acc(xs, sWin, r0, c0, acc);
#pragma unroll
    for (int i = 0; i < 4; i++)
#pragma unroll
        for (int j = 0; j < 4; j++) hs[(r0 + i) * RS + c0 + j] = fmaxf(acc[i][j], 0.f);
    __syncthreads();

    // a_src
#pragma unroll
    for (int i = 0; i < 4; i++)
#pragma unroll
        for (int j = 0; j < 4; j++) acc[i][j] = 0.f;
    gemm64_acc(hs, sWs, r0, c0, acc);
#pragma unroll
    for (int i = 0; i < 4; i++) {
        int row = base + r0 + i;
        if (row < N) *(float4*)(g_asrc + row * 64 + c0) =
            make_float4(acc[i][0], acc[i][1], acc[i][2], acc[i][3]);
    }

    // a_dst
#pragma unroll
    for (int i = 0; i < 4; i++)
#pragma unroll
        for (int j = 0; j < 4; j++) acc[i][j] = 0.f;
    gemm64_acc(hs, sWd, r0, c0, acc);
#pragma unroll
    for (int i = 0; i < 4; i++) {
        int row = base + r0 + i;
        if (row < N) *(float4*)(g_adst + row * 64 + c0) =
            make_float4(acc[i][0], acc[i][1], acc[i][2], acc[i][3]);
    }

    // v
#pragma unroll
    for (int i = 0; i < 4; i++)
#pragma unroll
        for (int j = 0; j < 4; j++) acc[i][j] = 0.f;
    gemm64_acc(hs, sWl, r0, c0, acc);
#pragma unroll
    for (int i = 0; i < 4; i++) {
        int row = base + r0 + i;
        if (row < N) *(float4*)(g_v + row * 64 + c0) =
            make_float4(acc[i][0], acc[i][1], acc[i][2], acc[i][3]);
    }
}

// ---------------- K2: per-edge MLPs, exp(alpha), scatter-sum of exp ----------------
__global__ void __launch_bounds__(256, 2) k_edge1(
    const float* __restrict__ pos, const int* __restrict__ ei,
    const float* __restrict__ Wp1, const float* __restrict__ bp1,
    const float* __restrict__ Wp2, const float* __restrict__ bp2,
    const float* __restrict__ Wa1, const float* __restrict__ ba1,
    const float* __restrict__ Wa2, const float* __restrict__ ba2,
    int N, int E)
{
    extern __shared__ float sm[];
    float* sWp1 = sm;                 // [6][64]
    float* sWp2 = sWp1 + 384;         // [64][64]
    float* sWa1 = sWp2 + 4096;
    float* sWa2 = sWa1 + 4096;
    float* sbp1 = sWa2 + 4096;        // 64
    float* sbp2 = sbp1 + 64;
    float* sba1 = sbp2 + 64;
    float* sba2 = sba1 + 64;
    float* bufA = sba2 + 64;          // [64][RS]
    float* bufB = bufA + 64 * RS;     // [64][RS]
    float* sPos = bufB + 64 * RS;     // [64][8]
    int*   sSrc = (int*)(sPos + 64 * 8);  // 64
    int*   sDst = sSrc + 64;              // 64

    const int tid = threadIdx.x;
    for (int i = tid; i < 384;  i += 256) sWp1[i] = Wp1[i];
    for (int i = tid; i < 4096; i += 256) { sWp2[i] = Wp2[i]; sWa1[i] = Wa1[i]; sWa2[i] = Wa2[i]; }
    if (tid < 64) { sbp1[tid] = bp1[tid]; sbp2[tid] = bp2[tid]; sba1[tid] = ba1[tid]; sba2[tid] = ba2[tid]; }

    const int TOT = N + E;
    const int NT  = (TOT + 63) >> 6;
    const int tr = tid >> 4, tc = tid & 15, r0 = tr * 4, c0 = tc * 4;

    for (int tile = blockIdx.x; tile < NT; tile += gridDim.x) {
        const int base = tile << 6;
        __syncthreads();   // protect smem reuse across loop iterations

        // indices
        if (tid < 64) {
            int eid = base + tid;
            int s = 0, d = 0;
            if (eid < TOT) {
                if (eid < E) { s = ei[eid]; d = ei[E + eid]; }
                else         { s = d = eid - E; }
            }
            sSrc[tid] = s; sDst[tid] = d;
        }
        __syncthreads();

        // pos diffs
        for (int i = tid; i < 384; i += 256) {
            int r = i / 6, c = i - r * 6;
            sPos[r * 8 + c] = pos[sDst[r] * 6 + c] - pos[sSrc[r] * 6 + c];
        }
        __syncthreads();

        // hidden1 = relu(posdiff @ Wp1 + bp1)   (K=6)
        for (int i = tid; i < 4096; i += 256) {
            int r = i >> 6, c = i & 63;
            float a = sbp1[c];
#pragma unroll
            for (int k = 0; k < 6; k++) a += sPos[r * 8 + k] * sWp1[k * 64 + c];
            bufA[r * RS + c] = fmaxf(a, 0.f);
        }
        __syncthreads();

        // delta = relu(hidden1 @ Wp2 + bp2); y = a_dst[d]-a_src[s]+delta; tvd = v[s]+delta
        float acc[4][4];
#pragma unroll
        for (int i = 0; i < 4; i++)
#pragma unroll
            for (int j = 0; j < 4; j++) acc[i][j] = sbp2[c0 + j];
        gemm64_acc(bufA, sWp2, r0, c0, acc);
#pragma unroll
        for (int i = 0; i < 4; i++) {
            int r = r0 + i;
            int s = sSrc[r], d = sDst[r];
            float4 ad = *(const float4*)(g_adst + d * 64 + c0);
            float4 as = *(const float4*)(g_asrc + s * 64 + c0);
            float4 vv = *(const float4*)(g_v    + s * 64 + c0);
            float d0 = fmaxf(acc[i][0], 0.f), d1 = fmaxf(acc[i][1], 0.f);
            float d2 = fmaxf(acc[i][2], 0.f), d3 = fmaxf(acc[i][3], 0.f);
            bufB[r * RS + c0 + 0] = ad.x - as.x + d0;
            bufB[r * RS + c0 + 1] = ad.y - as.y + d1;
            bufB[r * RS + c0 + 2] = ad.z - as.z + d2;
            bufB[r * RS + c0 + 3] = ad.w - as.w + d3;
            int eid = base + r;
            if (eid < TOT)
                *(float4*)(g_tvd + (size_t)eid * 64 + c0) =
                    make_float4(vv.x + d0, vv.y + d1, vv.z + d2, vv.w + d3);
        }
        __syncthreads();

        // hidden2 = relu(y @ Wa1 + ba1)
#pragma unroll
        for (int i = 0; i < 4; i++)
#pragma unroll
            for (int j = 0; j < 4; j++) acc[i][j] = sba1[c0 + j];
        gemm64_acc(bufB, sWa1, r0, c0, acc);
#pragma unroll
        for (int i = 0; i < 4; i++)
#pragma unroll
            for (int j = 0; j < 4; j++) bufA[(r0 + i) * RS + c0 + j] = fmaxf(acc[i][j], 0.f);
        __syncthreads();

        // alpha = relu(hidden2 @ Wa2 + ba2); e = exp(alpha); scatter
#pragma unroll
        for (int i = 0; i < 4; i++)
#pragma unroll
            for (int j = 0; j < 4; j++) acc[i][j] = sba2[c0 + j];
        gemm64_acc(bufA, sWa2, r0, c0, acc);
#pragma unroll
        for (int i = 0; i < 4; i++) {
            int r = r0 + i;
            int eid = base + r;
            if (eid < TOT) {
                int d = sDst[r];
                float e0 = expf(fmaxf(acc[i][0], 0.f));
                float e1 = expf(fmaxf(acc[i][1], 0.f));
                float e2 = expf(fmaxf(acc[i][2], 0.f));
                float e3 = expf(fmaxf(acc[i][3], 0.f));
                *(float4*)(g_eexp + (size_t)eid * 64 + c0) = make_float4(e0, e1, e2, e3);
                atomicAdd(&g_ssum[d * 64 + c0 + 0], e0);
                atomicAdd(&g_ssum[d * 64 + c0 + 1], e1);
                atomicAdd(&g_ssum[d * 64 + c0 + 2], e2);
                atomicAdd(&g_ssum[d * 64 + c0 + 3], e3);
            }
        }
    }
}

// ---------------- K3: msg = eexp * tvd / s[dst]; scatter-sum to out_acc ----------------
__global__ void __launch_bounds__(256) k_edge2(const int* __restrict__ ei, int N, int E)
{
    int idx = blockIdx.x * 256 + threadIdx.x;
    const int TOT = N + E;
    if (idx >= TOT * 16) return;
    int eid = idx >> 4;
    int c0  = (idx & 15) << 2;
    int d = (eid < E) ? ei[E + eid] : (eid - E);
    float4 e4 = *(const float4*)(g_eexp + (size_t)eid * 64 + c0);
    float4 t4 = *(const float4*)(g_tvd  + (size_t)eid * 64 + c0);
    float4 s4 = *(const float4*)(g_ssum + d * 64 + c0);
    atomicAdd(&g_oacc[d * 64 + c0 + 0], e4.x * t4.x / (s4.x + 1e-16f));
    atomicAdd(&g_oacc[d * 64 + c0 + 1], e4.y * t4.y / (s4.y + 1e-16f));
    atomicAdd(&g_oacc[d * 64 + c0 + 2], e4.z * t4.z / (s4.z + 1e-16f));
    atomicAdd(&g_oacc[d * 64 + c0 + 3], e4.w * t4.w / (s4.w + 1e-16f));
}

// ---------------- K4: out = relu(out_acc @ Wout + bout) + x ----------------
__global__ void __launch_bounds__(256) k_out(
    const float* __restrict__ x, const float* __restrict__ Wout,
    const float* __restrict__ bout, float* __restrict__ out, int N)
{
    extern __shared__ float sm[];
    float* sW = sm;
    float* sb = sW + 4096;
    float* As = sb + 64;  // [64][RS]
    const int tid = threadIdx.x;
    for (int i = tid; i < 4096; i += 256) sW[i] = Wout[i];
    if (tid < 64) sb[tid] = bout[tid];
    const int base = blockIdx.x * 64;
    for (int i = tid; i < 1024; i += 256) {
        int r = i >> 4, c4 = (i & 15) << 2;
        int row = base + r;
        float4 v = (row < N) ? *(const float4*)(g_oacc + row * 64 + c4)
                             : make_float4(0.f, 0.f, 0.f, 0.f);
        *(float4*)(As + r * RS + c4) = v;
    }
    __syncthreads();
    const int tr = tid >> 4, tc = tid & 15, r0 = tr * 4, c0 = tc * 4;
    float acc[4][4];
#pragma unroll
    for (int i = 0; i < 4; i++)
#pragma unroll
        for (int j = 0; j < 4; j++) acc[i][j] = sb[c0 + j];
    gemm64_acc(As, sW, r0, c0, acc);
#pragma unroll
    for (int i = 0; i < 4; i++) {
        int row = base + r0 + i;
        if (row < N) {
            float4 res = *(const float4*)(x + (size_t)row * 64 + c0);
            *(float4*)(out + (size_t)row * 64 + c0) =
                make_float4(fmaxf(acc[i][0], 0.f) + res.x,
                            fmaxf(acc[i][1], 0.f) + res.y,
                            fmaxf(acc[i][2], 0.f) + res.z,
                            fmaxf(acc[i][3], 0.f) + res.w);
        }
    }
}

// ---------------- host ----------------
extern "C" void kernel_launch(void* const* d_in, const int* in_sizes, int n_in,
                              void* d_out, int out_size)
{
    const float* x    = (const float*)d_in[0];
    const float* pos  = (const float*)d_in[1];
    const int*   ei   = (const int*)  d_in[2];
    const float* Win  = (const float*)d_in[3];
    const float* bin  = (const float*)d_in[4];
    const float* Wout = (const float*)d_in[5];
    const float* bout = (const float*)d_in[6];
    const float* Wlin = (const float*)d_in[7];
    const float* Wsrc = (const float*)d_in[8];
    const float* Wdst = (const float*)d_in[9];
    const float* Wp1  = (const float*)d_in[10];
    const float* bp1  = (const float*)d_in[11];
    const float* Wp2  = (const float*)d_in[12];
    const float* bp2  = (const float*)d_in[13];
    const float* Wa1  = (const float*)d_in[14];
    const float* ba1  = (const float*)d_in[15];
    const float* Wa2  = (const float*)d_in[16];
    const float* ba2  = (const float*)d_in[17];

    const int N = in_sizes[0] / 64;
    const int E = in_sizes[2] / 2;
    const int TOT = N + E;

    void *p_ssum, *p_oacc;
    cudaGetSymbolAddress(&p_ssum, g_ssum);
    cudaGetSymbolAddress(&p_oacc, g_oacc);
    cudaMemsetAsync(p_ssum, 0, (size_t)N * 64 * sizeof(float), 0);
    cudaMemsetAsync(p_oacc, 0, (size_t)N * 64 * sizeof(float), 0);

    const int smem_proj  = (4 * 4096 + 64 + 2 * 64 * RS) * 4;
    const int smem_edge1 = (384 + 3 * 4096 + 4 * 64 + 2 * 64 * RS + 64 * 8) * 4 + 128 * 4;
    const int smem_out   = (4096 + 64 + 64 * RS) * 4;

    cudaFuncSetAttribute(k_proj,  cudaFuncAttributeMaxDynamicSharedMemorySize, smem_proj);
    cudaFuncSetAttribute(k_edge1, cudaFuncAttributeMaxDynamicSharedMemorySize, smem_edge1);

    const int ntile_n = (N + 63) / 64;
    k_proj<<<ntile_n, 256, smem_proj>>>(x, Win, bin, Wsrc, Wdst, Wlin, N);
    k_edge1<<<296, 256, smem_edge1>>>(pos, ei, Wp1, bp1, Wp2, bp2, Wa1, ba1, Wa2, ba2, N, E);
    k_edge2<<<(TOT * 16 + 255) / 256, 256>>>(ei, N, E);
    k_out<<<ntile_n, 256, smem_out>>>(x, Wout, bout, (float*)d_out, N);
}